// round 2
// baseline (speedup 1.0000x reference)
#include <cuda_runtime.h>
#include <cuda_bf16.h>
#include <float.h>
#include <math.h>

#define BV 128
#define BT 64
#define EMB 512
#define NP 196
#define NR 197
#define NKEEP 118
#define NNON 78
#define KP 58
#define HID 102
#define MAXKT 100
#define TOK 60

// ---------------- device scratch ----------------
__device__ float g_inv[BV * NR];
__device__ float g_self[BV * NP];
__device__ float g_logits[BV * NP * KP];
__device__ float g_capglo[BT * EMB];
__device__ float g_selcap[BT * 30 * EMB];
__device__ int   g_nt[BT];
__device__ float g_score[BT * BV * NP];

__device__ __forceinline__ float gelu_f(float x) {
    return 0.5f * x * (1.0f + erff(x * 0.70710678118654752440f));
}

// block-wide sum for 256-thread blocks
__device__ __forceinline__ float bsum(float v, float* buf) {
    for (int o = 16; o; o >>= 1) v += __shfl_down_sync(0xffffffffu, v, o);
    int w = threadIdx.x >> 5, l = threadIdx.x & 31;
    if (l == 0) buf[w] = v;
    __syncthreads();
    float r = (threadIdx.x < 8) ? buf[threadIdx.x] : 0.0f;
    if (w == 0) {
        for (int o = 4; o; o >>= 1) r += __shfl_down_sync(0xffffffffu, r, o);
        if (l == 0) buf[0] = r;
    }
    __syncthreads();
    float res = buf[0];
    __syncthreads();
    return res;
}

// ---------------- K1: per-image norms, glo, self_attn ----------------
__global__ void __launch_bounds__(256) k1_img(const float* __restrict__ img) {
    int b = blockIdx.x;
    const float* base = img + (size_t)b * NR * EMB;
    __shared__ float sm[EMB];
    __shared__ float red[32];
    int tid = threadIdx.x;
    for (int c = tid; c < EMB; c += 256) {
        float s = 0.f;
        for (int j = 1; j < NR; ++j) s += base[(size_t)j * EMB + c];
        sm[c] = s * (1.0f / NP);
    }
    __syncthreads();
    float pv = 0.f;
    for (int c = tid; c < EMB; c += 256) { float v = sm[c]; pv += v * v; }
    float nn = bsum(pv, red);
    float rn = 1.f / fmaxf(sqrtf(nn), 1e-12f);
    for (int c = tid; c < EMB; c += 256) sm[c] *= rn;
    __syncthreads();
    int wid = tid >> 5, lane = tid & 31;
    for (int j = wid; j < NR; j += 8) {
        const float* r = base + (size_t)j * EMB;
        float s2 = 0.f, sd = 0.f;
        for (int k = lane; k < EMB; k += 32) { float v = r[k]; s2 += v * v; sd += v * sm[k]; }
        for (int o = 16; o; o >>= 1) {
            s2 += __shfl_down_sync(0xffffffffu, s2, o);
            sd += __shfl_down_sync(0xffffffffu, sd, o);
        }
        if (lane == 0) {
            float inv = 1.f / fmaxf(sqrtf(s2), 1e-12f);
            g_inv[b * NR + j] = inv;
            if (j >= 1) g_self[b * NP + j - 1] = sd * inv;
        }
    }
}

// ---------------- K2: caption-independent MLP logits ----------------
__global__ void __launch_bounds__(256) k2_logits(
    const float* __restrict__ img,
    const float* __restrict__ lng, const float* __restrict__ lnb,
    const float* __restrict__ w1, const float* __restrict__ b1,
    const float* __restrict__ w2, const float* __restrict__ b2) {
    extern __shared__ float w1s[];  // 512*102
    __shared__ float ln[2][EMB];
    __shared__ float gh[2][HID];
    __shared__ float red[32];
    int tid = threadIdx.x;
    for (int v = tid; v < EMB * HID; v += 256) w1s[v] = w1[v];
    int base = blockIdx.x * 64;
    for (int rr = 0; rr < 64; rr += 2) {
        __syncthreads();
        for (int r = 0; r < 2; ++r) {
            int grow = base + rr + r;
            int b = grow / NP, j = grow - b * NP;
            const float* src = img + ((size_t)(b * NR) + 1 + j) * EMB;
            for (int c = tid; c < EMB; c += 256) ln[r][c] = src[c];
        }
        __syncthreads();
        for (int r = 0; r < 2; ++r) {
            float p = 0.f;
            for (int c = tid; c < EMB; c += 256) p += ln[r][c];
            float mu = bsum(p, red) * (1.0f / EMB);
            p = 0.f;
            for (int c = tid; c < EMB; c += 256) { float d = ln[r][c] - mu; p += d * d; }
            float var = bsum(p, red) * (1.0f / EMB);
            float rstd = rsqrtf(var + 1e-5f);
            for (int c = tid; c < EMB; c += 256)
                ln[r][c] = (ln[r][c] - mu) * rstd * lng[c] + lnb[c];
            __syncthreads();
        }
        if (tid < 2 * HID) {
            int r = tid >= HID ? 1 : 0;
            int h = tid - r * HID;
            float a = 0.f;
            for (int c = 0; c < EMB; ++c) a += ln[r][c] * w1s[c * HID + h];
            gh[r][h] = gelu_f(a + b1[h]);
        }
        __syncthreads();
        if (tid < 2 * KP) {
            int r = tid >= KP ? 1 : 0;
            int p = tid - r * KP;
            float a = b2[p];
            for (int h = 0; h < HID; ++h) a += gh[r][h] * w2[h * KP + p];
            g_logits[(size_t)(base + rr + r) * KP + p] = a;
        }
    }
}

// ---------------- K3: per-caption ----------------
__global__ void __launch_bounds__(256) k3_cap(
    const float* __restrict__ cap, const int* __restrict__ lens,
    const float* __restrict__ lng, const float* __restrict__ lnb,
    const float* __restrict__ w1, const float* __restrict__ b1,
    const float* __restrict__ casc, const float* __restrict__ fw,
    const float* __restrict__ fb) {
    extern __shared__ float w1s[];   // 512*102, later overlaid with rowsb
    __shared__ float ln[2][EMB];
    __shared__ float gh[2][HID];
    __shared__ float lg[60 * 32];
    __shared__ float red[32];
    __shared__ float pb2[256];
    __shared__ float inv2[32];
    int i = blockIdx.x, tid = threadIdx.x;
    int n = lens[i], m = n - 1;
    int kt = m >> 1;
    kt = kt < 4 ? 4 : kt;
    kt = kt > MAXKT ? MAXKT : kt;
    if (kt > 29) kt = 29;
    const float* capi = cap + (size_t)i * 60 * EMB;
    // cap_glo
    for (int c = tid; c < EMB; c += 256) {
        float s = 0.f;
        for (int r = 0; r < n; ++r) s += capi[(size_t)r * EMB + c];
        ln[0][c] = s / (float)n;
    }
    __syncthreads();
    float pv = 0.f;
    for (int c = tid; c < EMB; c += 256) pv += ln[0][c] * ln[0][c];
    float nn = bsum(pv, red);
    float rn = 1.f / fmaxf(sqrtf(nn), 1e-12f);
    for (int c = tid; c < EMB; c += 256) g_capglo[i * EMB + c] = ln[0][c] * rn;
    for (int v = tid; v < EMB * HID; v += 256) w1s[v] = w1[v];
    __syncthreads();
    float cs = casc[0];
    for (int rw = 0; rw < m; rw += 2) {
        for (int r = 0; r < 2; ++r) {
            int wi = rw + r < m ? rw + r : m - 1;
            const float* src = capi + (size_t)(1 + wi) * EMB;
            for (int c = tid; c < EMB; c += 256) ln[r][c] = src[c];
        }
        __syncthreads();
        for (int r = 0; r < 2; ++r) {
            float p = 0.f;
            for (int c = tid; c < EMB; c += 256) p += ln[r][c];
            float mu = bsum(p, red) * (1.0f / EMB);
            p = 0.f;
            for (int c = tid; c < EMB; c += 256) { float d = ln[r][c] - mu; p += d * d; }
            float var = bsum(p, red) * (1.0f / EMB);
            float rstd = rsqrtf(var + 1e-5f);
            for (int c = tid; c < EMB; c += 256)
                ln[r][c] = (ln[r][c] - mu) * rstd * lng[c] + lnb[c];
            __syncthreads();
        }
        if (tid < 2 * HID) {
            int r = tid >= HID ? 1 : 0;
            int h = tid - r * HID;
            float a = 0.f;
            for (int c = 0; c < EMB; ++c) a += ln[r][c] * w1s[c * HID + h];
            gh[r][h] = gelu_f(a + b1[h]);
        }
        __syncthreads();
        if (tid < 64) {
            int r = tid >> 5, t = tid & 31;
            int rowg = rw + r;
            if (t < kt && rowg < m) {
                float a = fb[i * MAXKT + t];
                for (int h = 0; h < HID; ++h)
                    a += gh[r][h] * fw[((size_t)i * HID + h) * MAXKT + t];
                lg[rowg * 32 + t] = a;
            }
        }
        __syncthreads();
    }
    if (tid < kt) {
        float mx = -FLT_MAX;
        for (int r = 0; r < m; ++r) mx = fmaxf(mx, lg[r * 32 + tid] * cs);
        float z = 0.f;
        for (int r = 0; r < m; ++r) {
            float e = expf(lg[r * 32 + tid] * cs - mx);
            lg[r * 32 + tid] = e; z += e;
        }
        float iz = 1.f / z;
        for (int r = 0; r < m; ++r) lg[r * 32 + tid] *= iz;
    }
    __syncthreads();
    float accA[29], accB[29];
#pragma unroll
    for (int t = 0; t < 29; ++t) { accA[t] = 0.f; accB[t] = 0.f; }
    for (int r = 0; r < m; ++r) {
        float xa = capi[(size_t)(1 + r) * EMB + tid];
        float xb = capi[(size_t)(1 + r) * EMB + tid + 256];
#pragma unroll
        for (int t = 0; t < 29; ++t) {
            if (t < kt) { float w = lg[r * 32 + t]; accA[t] += w * xa; accB[t] += w * xb; }
        }
    }
    __syncthreads();   // w1s no longer needed -> overlay
    float* rowsb = w1s;                // 30*513 floats
    rowsb[tid] = capi[tid];
    rowsb[tid + 256] = capi[tid + 256];
#pragma unroll
    for (int t = 0; t < 29; ++t) {
        if (t < kt) {
            rowsb[(1 + t) * 513 + tid] = accA[t];
            rowsb[(1 + t) * 513 + tid + 256] = accB[t];
        }
    }
    __syncthreads();
    {
        int rrow = tid & 31, q = tid >> 5;
        float s = 0.f;
        if (rrow <= kt) {
            const float* rp = rowsb + rrow * 513 + q * 64;
            for (int k = 0; k < 64; ++k) s += rp[k] * rp[k];
        }
        pb2[q * 32 + rrow] = s;
    }
    __syncthreads();
    if (tid < 32 && tid <= kt) {
        float s = 0.f;
#pragma unroll
        for (int q = 0; q < 8; ++q) s += pb2[q * 32 + tid];
        inv2[tid] = 1.f / fmaxf(sqrtf(s), 1e-12f);
    }
    __syncthreads();
    for (int t = 0; t <= kt; ++t) {
        float iv = inv2[t];
        g_selcap[((size_t)i * 30 + t) * EMB + tid] = rowsb[t * 513 + tid] * iv;
        g_selcap[((size_t)i * 30 + t) * EMB + tid + 256] = rowsb[t * 513 + tid + 256] * iv;
    }
    if (tid == 0) g_nt[i] = kt + 1;
}

// ---------------- K4: score[i][b][j] ----------------
__global__ void __launch_bounds__(256) k4_score(const float* __restrict__ img) {
    extern __shared__ float cg[];    // 64*513
    __shared__ float xr[EMB];
    __shared__ float part[256];
    int tid = threadIdx.x;
    int b = blockIdx.y;
    for (int v = tid; v < BT * EMB; v += 256) {
        int ci = v >> 9, c = v & 511;
        cg[ci * 513 + c] = g_capglo[v];
    }
    __syncthreads();
    int j0 = blockIdx.x * 49;
    for (int jj = 0; jj < 49; ++jj) {
        int j = j0 + jj;
        const float* rp = img + ((size_t)(b * NR) + 1 + j) * EMB;
        for (int c = tid; c < EMB; c += 256) xr[c] = rp[c];
        __syncthreads();
        int ii = tid & 63, q = tid >> 6;
        float s = 0.f;
        int c0 = q * 128;
        for (int c = c0; c < c0 + 128; ++c) s += xr[c] * cg[ii * 513 + c];
        part[q * 64 + ii] = s;
        __syncthreads();
        if (tid < 64) {
            float d = part[tid] + part[64 + tid] + part[128 + tid] + part[192 + tid];
            g_score[((size_t)tid * BV + b) * NP + j] =
                g_self[b * NP + j] + d * g_inv[b * NR + 1 + j];
        }
        __syncthreads();
    }
}

// ---------------- K5: per (caption, image) pair ----------------
__global__ void __launch_bounds__(256, 1) k5_pair(
    const float* __restrict__ img, const float* __restrict__ tasc_p,
    float* __restrict__ out) {
    extern __shared__ float dsm[];
    float* R = dsm;                 // 60*512
    float* W = dsm + TOK * EMB;     // 118*60
    __shared__ float sc[256];
    __shared__ float ssort[256];
    __shared__ int keptidx[NKEEP];
    __shared__ int nonidx[NNON];
    __shared__ int cnts[2];
    __shared__ float wnon[NNON];
    __shared__ float red[32];
    __shared__ float rinv[TOK];
    __shared__ float simbuf[30 * TOK];
    int tid = threadIdx.x;
    int i = blockIdx.x, b = blockIdx.y;
    const float* imb = img + (size_t)b * NR * EMB;

    float v = (tid < NP) ? g_score[((size_t)i * BV + b) * NP + tid] : -FLT_MAX;
    sc[tid] = v;
    ssort[tid] = v;
    if (tid < NKEEP) keptidx[tid] = 0;
    if (tid < NNON) nonidx[tid] = 0;
    if (tid == 0) { cnts[0] = 0; cnts[1] = 0; }
    __syncthreads();
    // bitonic sort ascending (values only)
    for (int k = 2; k <= 256; k <<= 1) {
        for (int j = k >> 1; j > 0; j >>= 1) {
            int ix = tid ^ j;
            float a = ssort[tid], c = ssort[ix];
            bool up = ((tid & k) == 0);
            float r2;
            if (ix > tid) r2 = up ? fminf(a, c) : fmaxf(a, c);
            else          r2 = up ? fmaxf(a, c) : fminf(a, c);
            __syncthreads();
            ssort[tid] = r2;
            __syncthreads();
        }
    }
    float thrv = ssort[138];   // 118th largest
    float nmax = ssort[137];   // max of non-kept
    if (tid < NP) {
        float s = sc[tid];
        if (s >= thrv) {
            int p = atomicAdd(&cnts[0], 1);
            if (p < NKEEP) keptidx[p] = tid;
        } else {
            int p = atomicAdd(&cnts[1], 1);
            if (p < NNON) nonidx[p] = tid;
        }
    }
    __syncthreads();
    // non-kept softmax + extra row
    if (tid < NNON) wnon[tid] = expf(sc[nonidx[tid]] - nmax);
    __syncthreads();
    float nsum = bsum(tid < NNON ? wnon[tid] : 0.f, red);
    float invns = 1.f / nsum;
    {
        float e0 = 0.f, e1 = 0.f;
        for (int q = 0; q < NNON; ++q) {
            const float* xr = imb + (size_t)(1 + nonidx[q]) * EMB;
            float w = wnon[q];
            e0 += w * xr[tid];
            e1 += w * xr[tid + 256];
        }
        R[59 * EMB + tid] = e0 * invns;
        R[59 * EMB + tid + 256] = e1 * invns;
        R[tid] = imb[tid];
        R[tid + 256] = imb[tid + 256];
    }
    // logits -> W
    float tasc = tasc_p[0];
    for (int v2 = tid; v2 < NKEEP * KP; v2 += 256) {
        int n = v2 / KP, p = v2 - n * KP;
        W[n * 60 + p] = g_logits[((size_t)(b * NP) + keptidx[n]) * KP + p] * tasc;
    }
    __syncthreads();
    if (tid < KP) {
        float mx = -FLT_MAX;
        for (int n = 0; n < NKEEP; ++n) mx = fmaxf(mx, W[n * 60 + tid]);
        float z = 0.f;
        for (int n = 0; n < NKEEP; ++n) {
            float e = expf(W[n * 60 + tid] - mx);
            W[n * 60 + tid] = e; z += e;
        }
        float iz = 1.f / z;
        for (int n = 0; n < NKEEP; ++n) W[n * 60 + tid] *= iz;
    }
    __syncthreads();
    // aggr: thread = (p-half H, column base cb), 4 columns, 29 p's
    {
        float a0[29], a1[29], a2[29], a3[29];
#pragma unroll
        for (int t = 0; t < 29; ++t) { a0[t] = a1[t] = a2[t] = a3[t] = 0.f; }
        int H = tid >> 7;
        int cb = tid & 127;
        for (int n = 0; n < NKEEP; ++n) {
            const float* xr = imb + (size_t)(1 + keptidx[n]) * EMB;
            float x0 = xr[cb], x1 = xr[cb + 128], x2 = xr[cb + 256], x3 = xr[cb + 384];
            const float* wp = W + n * 60 + H * 29;
#pragma unroll
            for (int t = 0; t < 29; ++t) {
                float w = wp[t];
                a0[t] += w * x0; a1[t] += w * x1; a2[t] += w * x2; a3[t] += w * x3;
            }
        }
#pragma unroll
        for (int t = 0; t < 29; ++t) {
            int p = H * 29 + t;
            float* rr = R + (size_t)(1 + p) * EMB;
            rr[cb] = a0[t]; rr[cb + 128] = a1[t]; rr[cb + 256] = a2[t]; rr[cb + 384] = a3[t];
        }
    }
    __syncthreads();
    // row inverse norms
    int wid = tid >> 5, lane = tid & 31;
    for (int rrow = wid; rrow < TOK; rrow += 8) {
        const float* rp = R + rrow * EMB;
        float s = 0.f;
        for (int c = lane; c < EMB; c += 32) { float x = rp[c]; s += x * x; }
        for (int o = 16; o; o >>= 1) s += __shfl_down_sync(0xffffffffu, s, o);
        if (lane == 0) rinv[rrow] = 1.f / fmaxf(sqrtf(s), 1e-12f);
    }
    __syncthreads();
    // sim
    int T = g_nt[i];
    const float* scap = g_selcap + (size_t)i * 30 * EMB;
    int npair = T * TOK;
    for (int pr = wid; pr < npair; pr += 8) {
        int t = pr / TOK, tok = pr - t * TOK;
        const float4* cv = (const float4*)(scap + (size_t)t * EMB);
        const float4* rv = (const float4*)(R + (size_t)tok * EMB);
        float s = 0.f;
        for (int q = lane; q < 128; q += 32) {
            float4 a = cv[q], c = rv[q];
            s += a.x * c.x + a.y * c.y + a.z * c.z + a.w * c.w;
        }
        for (int o = 16; o; o >>= 1) s += __shfl_down_sync(0xffffffffu, s, o);
        if (lane == 0) simbuf[t * TOK + tok] = s * rinv[tok];
    }
    __syncthreads();
    if (tid < T) {
        float mx = -FLT_MAX;
        for (int tok = 0; tok < TOK; ++tok) mx = fmaxf(mx, simbuf[tid * TOK + tok]);
        simbuf[tid * TOK] = mx;
    }
    __syncthreads();
    if (tid == 0) {
        float s = 0.f;
        for (int t = 0; t < T; ++t) s += simbuf[t * TOK];
        out[b * BT + i] = s / (float)T;
    }
}

extern "C" void kernel_launch(void* const* d_in, const int* in_sizes, int n_in,
                              void* d_out, int out_size) {
    const float* img   = (const float*)d_in[0];
    const float* cap   = (const float*)d_in[1];
    const int*   lens  = (const int*)d_in[2];
    const float* talng = (const float*)d_in[3];
    const float* talnb = (const float*)d_in[4];
    const float* taw1  = (const float*)d_in[5];
    const float* tab1  = (const float*)d_in[6];
    const float* taw2  = (const float*)d_in[7];
    const float* tab2  = (const float*)d_in[8];
    const float* tasc  = (const float*)d_in[9];
    const float* calng = (const float*)d_in[10];
    const float* calnb = (const float*)d_in[11];
    const float* caw1  = (const float*)d_in[12];
    const float* cab1  = (const float*)d_in[13];
    const float* casc  = (const float*)d_in[14];
    const float* fw    = (const float*)d_in[15];
    const float* fb    = (const float*)d_in[16];
    float* out = (float*)d_out;

    cudaFuncSetAttribute(k2_logits, cudaFuncAttributeMaxDynamicSharedMemorySize, 208896);
    cudaFuncSetAttribute(k3_cap,    cudaFuncAttributeMaxDynamicSharedMemorySize, 208896);
    cudaFuncSetAttribute(k4_score,  cudaFuncAttributeMaxDynamicSharedMemorySize, 131328);
    cudaFuncSetAttribute(k5_pair,   cudaFuncAttributeMaxDynamicSharedMemorySize, 151200);

    k1_img<<<BV, 256>>>(img);
    k2_logits<<<392, 256, 208896>>>(img, talng, talnb, taw1, tab1, taw2, tab2);
    k3_cap<<<BT, 256, 208896>>>(cap, lens, calng, calnb, caw1, cab1, casc, fw, fb);
    k4_score<<<dim3(4, BV), 256, 131328>>>(img);
    k5_pair<<<dim3(BT, BV), 256, 151200>>>(img, tasc, out);
}

// round 3
// speedup vs baseline: 1.3596x; 1.3596x over previous
#include <cuda_runtime.h>
#include <cuda_bf16.h>
#include <float.h>
#include <math.h>

#define BV 128
#define BT 64
#define EMB 512
#define NP 196
#define NR 197
#define NKEEP 118
#define NNON 78
#define KP 58
#define HID 102
#define MAXKT 100
#define TOK 60

typedef unsigned long long ull;

// ---------------- device scratch ----------------
__device__ float g_inv[BV * NR];
__device__ float g_self[BV * NP];
__device__ float g_logits[BV * NP * KP];
__device__ float g_capglo[BT * EMB];
__device__ float g_selcap[BT * 30 * EMB];
__device__ int   g_nt[BT];
__device__ float g_score[BT * BV * NP];

__device__ __forceinline__ float gelu_f(float x) {
    return 0.5f * x * (1.0f + erff(x * 0.70710678118654752440f));
}

__device__ __forceinline__ ull pk2(float lo, float hi) {
    ull r; asm("mov.b64 %0,{%1,%2};" : "=l"(r) : "f"(lo), "f"(hi)); return r;
}
__device__ __forceinline__ void fma2(ull& a, ull x, ull w) {
    asm("fma.rn.f32x2 %0,%1,%2,%0;" : "+l"(a) : "l"(x), "l"(w));
}
__device__ __forceinline__ float2 upk2(ull a) {
    float lo, hi; asm("mov.b64 {%0,%1},%2;" : "=f"(lo), "=f"(hi) : "l"(a));
    return make_float2(lo, hi);
}

// float -> order-preserving uint key
__device__ __forceinline__ unsigned f2k(float f) {
    unsigned u = __float_as_uint(f);
    return (u & 0x80000000u) ? ~u : (u | 0x80000000u);
}

// block-wide sum for 256-thread blocks
__device__ __forceinline__ float bsum(float v, float* buf) {
    for (int o = 16; o; o >>= 1) v += __shfl_down_sync(0xffffffffu, v, o);
    int w = threadIdx.x >> 5, l = threadIdx.x & 31;
    if (l == 0) buf[w] = v;
    __syncthreads();
    float r = (threadIdx.x < 8) ? buf[threadIdx.x] : 0.0f;
    if (w == 0) {
        for (int o = 4; o; o >>= 1) r += __shfl_down_sync(0xffffffffu, r, o);
        if (l == 0) buf[0] = r;
    }
    __syncthreads();
    float res = buf[0];
    __syncthreads();
    return res;
}

// ---------------- K1: per-image norms, glo, self_attn ----------------
__global__ void __launch_bounds__(256) k1_img(const float* __restrict__ img) {
    int b = blockIdx.x;
    const float* base = img + (size_t)b * NR * EMB;
    __shared__ float sm[EMB];
    __shared__ float red[32];
    int tid = threadIdx.x;
    for (int c = tid; c < EMB; c += 256) {
        float s = 0.f;
        for (int j = 1; j < NR; ++j) s += base[(size_t)j * EMB + c];
        sm[c] = s * (1.0f / NP);
    }
    __syncthreads();
    float pv = 0.f;
    for (int c = tid; c < EMB; c += 256) { float v = sm[c]; pv += v * v; }
    float nn = bsum(pv, red);
    float rn = 1.f / fmaxf(sqrtf(nn), 1e-12f);
    for (int c = tid; c < EMB; c += 256) sm[c] *= rn;
    __syncthreads();
    int wid = tid >> 5, lane = tid & 31;
    for (int j = wid; j < NR; j += 8) {
        const float* r = base + (size_t)j * EMB;
        float s2 = 0.f, sd = 0.f;
        for (int k = lane; k < EMB; k += 32) { float v = r[k]; s2 += v * v; sd += v * sm[k]; }
        for (int o = 16; o; o >>= 1) {
            s2 += __shfl_down_sync(0xffffffffu, s2, o);
            sd += __shfl_down_sync(0xffffffffu, sd, o);
        }
        if (lane == 0) {
            float inv = 1.f / fmaxf(sqrtf(s2), 1e-12f);
            g_inv[b * NR + j] = inv;
            if (j >= 1) g_self[b * NP + j - 1] = sd * inv;
        }
    }
}

// ---------------- K2: caption-independent MLP logits ----------------
__global__ void __launch_bounds__(256) k2_logits(
    const float* __restrict__ img,
    const float* __restrict__ lng, const float* __restrict__ lnb,
    const float* __restrict__ w1, const float* __restrict__ b1,
    const float* __restrict__ w2, const float* __restrict__ b2) {
    extern __shared__ float w1s[];  // 512*102
    __shared__ float ln[2][EMB];
    __shared__ float gh[2][HID];
    __shared__ float red[32];
    int tid = threadIdx.x;
    for (int v = tid; v < EMB * HID; v += 256) w1s[v] = w1[v];
    int base = blockIdx.x * 64;
    for (int rr = 0; rr < 64; rr += 2) {
        __syncthreads();
        for (int r = 0; r < 2; ++r) {
            int grow = base + rr + r;
            int b = grow / NP, j = grow - b * NP;
            const float* src = img + ((size_t)(b * NR) + 1 + j) * EMB;
            for (int c = tid; c < EMB; c += 256) ln[r][c] = src[c];
        }
        __syncthreads();
        for (int r = 0; r < 2; ++r) {
            float p = 0.f;
            for (int c = tid; c < EMB; c += 256) p += ln[r][c];
            float mu = bsum(p, red) * (1.0f / EMB);
            p = 0.f;
            for (int c = tid; c < EMB; c += 256) { float d = ln[r][c] - mu; p += d * d; }
            float var = bsum(p, red) * (1.0f / EMB);
            float rstd = rsqrtf(var + 1e-5f);
            for (int c = tid; c < EMB; c += 256)
                ln[r][c] = (ln[r][c] - mu) * rstd * lng[c] + lnb[c];
            __syncthreads();
        }
        if (tid < 2 * HID) {
            int r = tid >= HID ? 1 : 0;
            int h = tid - r * HID;
            float a = 0.f;
            for (int c = 0; c < EMB; ++c) a += ln[r][c] * w1s[c * HID + h];
            gh[r][h] = gelu_f(a + b1[h]);
        }
        __syncthreads();
        if (tid < 2 * KP) {
            int r = tid >= KP ? 1 : 0;
            int p = tid - r * KP;
            float a = b2[p];
            for (int h = 0; h < HID; ++h) a += gh[r][h] * w2[h * KP + p];
            g_logits[(size_t)(base + rr + r) * KP + p] = a;
        }
    }
}

// ---------------- K3: per-caption ----------------
__global__ void __launch_bounds__(256) k3_cap(
    const float* __restrict__ cap, const int* __restrict__ lens,
    const float* __restrict__ lng, const float* __restrict__ lnb,
    const float* __restrict__ w1, const float* __restrict__ b1,
    const float* __restrict__ casc, const float* __restrict__ fw,
    const float* __restrict__ fb) {
    extern __shared__ float w1s[];   // 512*102, later overlaid with rowsb
    __shared__ float ln[2][EMB];
    __shared__ float gh[2][HID];
    __shared__ float lg[60 * 32];
    __shared__ float red[32];
    __shared__ float pb2[256];
    __shared__ float inv2[32];
    int i = blockIdx.x, tid = threadIdx.x;
    int n = lens[i], m = n - 1;
    int kt = m >> 1;
    kt = kt < 4 ? 4 : kt;
    kt = kt > MAXKT ? MAXKT : kt;
    if (kt > 29) kt = 29;
    const float* capi = cap + (size_t)i * 60 * EMB;
    for (int c = tid; c < EMB; c += 256) {
        float s = 0.f;
        for (int r = 0; r < n; ++r) s += capi[(size_t)r * EMB + c];
        ln[0][c] = s / (float)n;
    }
    __syncthreads();
    float pv = 0.f;
    for (int c = tid; c < EMB; c += 256) pv += ln[0][c] * ln[0][c];
    float nn = bsum(pv, red);
    float rn = 1.f / fmaxf(sqrtf(nn), 1e-12f);
    for (int c = tid; c < EMB; c += 256) g_capglo[i * EMB + c] = ln[0][c] * rn;
    for (int v = tid; v < EMB * HID; v += 256) w1s[v] = w1[v];
    __syncthreads();
    float cs = casc[0];
    for (int rw = 0; rw < m; rw += 2) {
        for (int r = 0; r < 2; ++r) {
            int wi = rw + r < m ? rw + r : m - 1;
            const float* src = capi + (size_t)(1 + wi) * EMB;
            for (int c = tid; c < EMB; c += 256) ln[r][c] = src[c];
        }
        __syncthreads();
        for (int r = 0; r < 2; ++r) {
            float p = 0.f;
            for (int c = tid; c < EMB; c += 256) p += ln[r][c];
            float mu = bsum(p, red) * (1.0f / EMB);
            p = 0.f;
            for (int c = tid; c < EMB; c += 256) { float d = ln[r][c] - mu; p += d * d; }
            float var = bsum(p, red) * (1.0f / EMB);
            float rstd = rsqrtf(var + 1e-5f);
            for (int c = tid; c < EMB; c += 256)
                ln[r][c] = (ln[r][c] - mu) * rstd * lng[c] + lnb[c];
            __syncthreads();
        }
        if (tid < 2 * HID) {
            int r = tid >= HID ? 1 : 0;
            int h = tid - r * HID;
            float a = 0.f;
            for (int c = 0; c < EMB; ++c) a += ln[r][c] * w1s[c * HID + h];
            gh[r][h] = gelu_f(a + b1[h]);
        }
        __syncthreads();
        if (tid < 64) {
            int r = tid >> 5, t = tid & 31;
            int rowg = rw + r;
            if (t < kt && rowg < m) {
                float a = fb[i * MAXKT + t];
                for (int h = 0; h < HID; ++h)
                    a += gh[r][h] * fw[((size_t)i * HID + h) * MAXKT + t];
                lg[rowg * 32 + t] = a;
            }
        }
        __syncthreads();
    }
    if (tid < kt) {
        float mx = -FLT_MAX;
        for (int r = 0; r < m; ++r) mx = fmaxf(mx, lg[r * 32 + tid] * cs);
        float z = 0.f;
        for (int r = 0; r < m; ++r) {
            float e = expf(lg[r * 32 + tid] * cs - mx);
            lg[r * 32 + tid] = e; z += e;
        }
        float iz = 1.f / z;
        for (int r = 0; r < m; ++r) lg[r * 32 + tid] *= iz;
    }
    __syncthreads();
    float accA[29], accB[29];
#pragma unroll
    for (int t = 0; t < 29; ++t) { accA[t] = 0.f; accB[t] = 0.f; }
    for (int r = 0; r < m; ++r) {
        float xa = capi[(size_t)(1 + r) * EMB + tid];
        float xb = capi[(size_t)(1 + r) * EMB + tid + 256];
#pragma unroll
        for (int t = 0; t < 29; ++t) {
            if (t < kt) { float w = lg[r * 32 + t]; accA[t] += w * xa; accB[t] += w * xb; }
        }
    }
    __syncthreads();
    float* rowsb = w1s;
    rowsb[tid] = capi[tid];
    rowsb[tid + 256] = capi[tid + 256];
#pragma unroll
    for (int t = 0; t < 29; ++t) {
        if (t < kt) {
            rowsb[(1 + t) * 513 + tid] = accA[t];
            rowsb[(1 + t) * 513 + tid + 256] = accB[t];
        }
    }
    __syncthreads();
    {
        int rrow = tid & 31, q = tid >> 5;
        float s = 0.f;
        if (rrow <= kt) {
            const float* rp = rowsb + rrow * 513 + q * 64;
            for (int k = 0; k < 64; ++k) s += rp[k] * rp[k];
        }
        pb2[q * 32 + rrow] = s;
    }
    __syncthreads();
    if (tid < 32 && tid <= kt) {
        float s = 0.f;
#pragma unroll
        for (int q = 0; q < 8; ++q) s += pb2[q * 32 + tid];
        inv2[tid] = 1.f / fmaxf(sqrtf(s), 1e-12f);
    }
    __syncthreads();
    for (int t = 0; t <= kt; ++t) {
        float iv = inv2[t];
        g_selcap[((size_t)i * 30 + t) * EMB + tid] = rowsb[t * 513 + tid] * iv;
        g_selcap[((size_t)i * 30 + t) * EMB + tid + 256] = rowsb[t * 513 + tid + 256] * iv;
    }
    if (tid == 0) g_nt[i] = kt + 1;
}

// ---------------- K4: register-tiled score GEMM (block = 1 image) ----------------
__global__ void __launch_bounds__(256) k4_score(const float* __restrict__ img) {
    extern __shared__ float sh4[];
    float* cgT = sh4;                 // [512][64]
    float* xs  = sh4 + 512 * 64;      // [32][513]
    int b = blockIdx.x, tid = threadIdx.x;
    for (int v = tid; v < BT * EMB; v += 256) {
        int cp = v >> 9, c = v & 511;
        cgT[c * 64 + cp] = g_capglo[v];
    }
    __syncthreads();
    int capg = tid & 15;      // 4 captions: capg*4 ..
    int rowg = tid >> 4;      // 2 rows: rowg*2 ..
    for (int chunk = 0; chunk < 7; ++chunk) {
        int jbase = chunk * 32;
        for (int v = tid; v < 32 * 512; v += 256) {
            int r = v >> 9, c = v & 511;
            int j = jbase + r;
            xs[r * 513 + c] = (j < NP) ? img[((size_t)(b * NR) + 1 + j) * EMB + c] : 0.f;
        }
        __syncthreads();
        ull a00 = 0, a01 = 0, a10 = 0, a11 = 0;
        const float* cgp = cgT + capg * 4;
        const float* x0p = xs + (rowg * 2) * 513;
        const float* x1p = x0p + 513;
        for (int c = 0; c < 512; ++c) {
            ull cgA = *(const ull*)(cgp + c * 64);
            ull cgB = *(const ull*)(cgp + c * 64 + 2);
            float x0 = x0p[c], x1 = x1p[c];
            ull X0 = pk2(x0, x0), X1 = pk2(x1, x1);
            fma2(a00, X0, cgA); fma2(a01, X0, cgB);
            fma2(a10, X1, cgA); fma2(a11, X1, cgB);
        }
#pragma unroll
        for (int r = 0; r < 2; ++r) {
            int j = jbase + rowg * 2 + r;
            if (j < NP) {
                float inv = g_inv[b * NR + 1 + j];
                float slf = g_self[b * NP + j];
                float2 pA = upk2(r ? a10 : a00);
                float2 pB = upk2(r ? a11 : a01);
                int cap0 = capg * 4;
                g_score[((size_t)(cap0 + 0) * BV + b) * NP + j] = slf + pA.x * inv;
                g_score[((size_t)(cap0 + 1) * BV + b) * NP + j] = slf + pA.y * inv;
                g_score[((size_t)(cap0 + 2) * BV + b) * NP + j] = slf + pB.x * inv;
                g_score[((size_t)(cap0 + 3) * BV + b) * NP + j] = slf + pB.y * inv;
            }
        }
        __syncthreads();
    }
}

// ---------------- K5: per (caption, image) pair ----------------
__global__ void __launch_bounds__(256, 1) k5_pair(
    const float* __restrict__ img, const float* __restrict__ tasc_p,
    float* __restrict__ out) {
    extern __shared__ float dsm[];
    float* R = dsm;                          // 60*512 floats
    float2* Wd = (float2*)(dsm + TOK * EMB); // 118*58 float2 (w,w)
    __shared__ float sc[256];
    __shared__ unsigned keyArr[256];
    __shared__ int keptidx[NKEEP];
    __shared__ int nonidx[NNON];
    __shared__ int cnts[2];
    __shared__ float2 wnon2[NNON];
    __shared__ float red[32];
    __shared__ float rinv[TOK];
    __shared__ float simbuf[30 * TOK];
    int tid = threadIdx.x;
    int i = blockIdx.x, b = blockIdx.y;
    const float* imb = img + (size_t)b * NR * EMB;

    float v = (tid < NP) ? g_score[((size_t)i * BV + b) * NP + tid] : 0.f;
    unsigned key = (tid < NP) ? f2k(v) : 0u;
    sc[tid] = v;
    keyArr[tid] = key;
    if (tid == 0) { cnts[0] = 0; cnts[1] = 0; }

    // radix select: 118th largest key
    unsigned mask = 0, prefix = 0;
    int krem = NKEEP;
    for (int bb = 31; bb >= 0; --bb) {
        unsigned bit = 1u << bb;
        bool pred = ((key & mask) == prefix) && (key & bit);
        int cnt = __syncthreads_count(pred);
        if (cnt >= krem) prefix |= bit; else krem -= cnt;
        mask |= bit;
    }
    // partition
    bool isKept = false;
    if (tid < NP) {
        if (key > prefix) isKept = true;
        else if (key == prefix) {
            int r = 0;
            for (int j = 0; j < tid; ++j) if (keyArr[j] == prefix) ++r;
            isKept = (r < krem);
        }
        if (isKept) { int p = atomicAdd(&cnts[0], 1); keptidx[p] = tid; }
        else        { int p = atomicAdd(&cnts[1], 1); nonidx[p] = tid; }
    }
    // threshold value for softmax shift (all non-kept <= thrf)
    unsigned tu = (prefix & 0x80000000u) ? (prefix & 0x7FFFFFFFu) : ~prefix;
    float thrf = __uint_as_float(tu);
    __syncthreads();

    // non-kept softmax weights
    float e = 0.f;
    if (tid < NNON) {
        e = expf(sc[nonidx[tid]] - thrf);
        wnon2[tid] = make_float2(e, e);
    }
    float nsum = bsum(tid < NNON ? e : 0.f, red);
    float invns = 1.f / nsum;

    // row 0 (cls) + extra row (59), thread owns float2 column index tid
    {
        const float2* imb2 = (const float2*)imb;
        ull acc = 0;
#pragma unroll 4
        for (int q = 0; q < NNON; ++q) {
            ull x = *(const ull*)((const float2*)(imb + (size_t)(1 + nonidx[q]) * EMB) + tid);
            ull w = *(const ull*)(&wnon2[q]);
            fma2(acc, x, w);
        }
        float2 ev = upk2(acc);
        ((float2*)(R + 59 * EMB))[tid] = make_float2(ev.x * invns, ev.y * invns);
        ((float2*)R)[tid] = imb2[tid];
    }

    // load logits (scaled) into Wd.x
    float tasc = tasc_p[0];
    for (int v2 = tid; v2 < NKEEP * KP; v2 += 256) {
        int n = v2 / KP, p = v2 - n * KP;
        Wd[n * KP + p].x = g_logits[((size_t)(b * NP) + keptidx[n]) * KP + p] * tasc;
    }
    __syncthreads();
    // softmax over kept (n) per p, store duplicated (w,w)
    if (tid < KP) {
        float mx = -FLT_MAX;
        for (int n = 0; n < NKEEP; ++n) mx = fmaxf(mx, Wd[n * KP + tid].x);
        float z = 0.f;
        for (int n = 0; n < NKEEP; ++n) {
            float ee = expf(Wd[n * KP + tid].x - mx);
            Wd[n * KP + tid].x = ee; z += ee;
        }
        float iz = 1.f / z;
        for (int n = 0; n < NKEEP; ++n) {
            float w = Wd[n * KP + tid].x * iz;
            Wd[n * KP + tid] = make_float2(w, w);
        }
    }
    __syncthreads();

    // aggr: thread = (H = p-half, c2 = float2 col), 29 p x 4 cols via f32x2
    {
        int H = tid >> 7;
        int c2 = tid & 127;
        ull acc01[29], acc23[29];
#pragma unroll
        for (int t = 0; t < 29; ++t) { acc01[t] = 0; acc23[t] = 0; }
        const float2* xr2 = (const float2*)(imb + (size_t)(1 + keptidx[0]) * EMB);
        ull nX01 = *(const ull*)(xr2 + c2);
        ull nX23 = *(const ull*)(xr2 + c2 + 128);
        const ull* wbase = (const ull*)Wd + H * 29;
        for (int n = 0; n < NKEEP; ++n) {
            ull X01 = nX01, X23 = nX23;
            if (n + 1 < NKEEP) {
                const float2* nx = (const float2*)(imb + (size_t)(1 + keptidx[n + 1]) * EMB);
                nX01 = *(const ull*)(nx + c2);
                nX23 = *(const ull*)(nx + c2 + 128);
            }
            const ull* wrow = wbase + n * KP;
#pragma unroll
            for (int t = 0; t < 29; ++t) {
                ull ww = wrow[t];
                fma2(acc01[t], X01, ww);
                fma2(acc23[t], X23, ww);
            }
        }
#pragma unroll
        for (int t = 0; t < 29; ++t) {
            int p = H * 29 + t;
            float2* rr = (float2*)(R + (size_t)(1 + p) * EMB);
            rr[c2] = upk2(acc01[t]);
            rr[c2 + 128] = upk2(acc23[t]);
        }
    }
    __syncthreads();

    // row inverse norms
    int wid = tid >> 5, lane = tid & 31;
    for (int rrow = wid; rrow < TOK; rrow += 8) {
        const float* rp = R + rrow * EMB;
        float s = 0.f;
        for (int c = lane; c < EMB; c += 32) { float x = rp[c]; s += x * x; }
        for (int o = 16; o; o >>= 1) s += __shfl_down_sync(0xffffffffu, s, o);
        if (lane == 0) rinv[rrow] = 1.f / fmaxf(sqrtf(s), 1e-12f);
    }
    __syncthreads();

    // sim: warp per (t, tok) pair, f32x2 dot
    int T = g_nt[i];
    const float* scap = g_selcap + (size_t)i * 30 * EMB;
    int npair = T * TOK;
    for (int pr = wid; pr < npair; pr += 8) {
        int t = pr / TOK, tok = pr - t * TOK;
        const ull* cv = (const ull*)(scap + (size_t)t * EMB);
        const ull* rv = (const ull*)(R + (size_t)tok * EMB);
        ull acc = 0;
#pragma unroll
        for (int q = 0; q < 8; ++q) {
            int idx = lane + q * 32;
            fma2(acc, cv[idx], rv[idx]);
        }
        float2 av = upk2(acc);
        float s = av.x + av.y;
        for (int o = 16; o; o >>= 1) s += __shfl_down_sync(0xffffffffu, s, o);
        if (lane == 0) simbuf[t * TOK + tok] = s * rinv[tok];
    }
    __syncthreads();
    if (tid < T) {
        float mx = -FLT_MAX;
        for (int tok = 0; tok < TOK; ++tok) mx = fmaxf(mx, simbuf[tid * TOK + tok]);
        simbuf[tid * TOK] = mx;
    }
    __syncthreads();
    if (tid == 0) {
        float s = 0.f;
        for (int t = 0; t < T; ++t) s += simbuf[t * TOK];
        out[b * BT + i] = s / (float)T;
    }
}

extern "C" void kernel_launch(void* const* d_in, const int* in_sizes, int n_in,
                              void* d_out, int out_size) {
    const float* img   = (const float*)d_in[0];
    const float* cap   = (const float*)d_in[1];
    const int*   lens  = (const int*)d_in[2];
    const float* talng = (const float*)d_in[3];
    const float* talnb = (const float*)d_in[4];
    const float* taw1  = (const float*)d_in[5];
    const float* tab1  = (const float*)d_in[6];
    const float* taw2  = (const float*)d_in[7];
    const float* tab2  = (const float*)d_in[8];
    const float* tasc  = (const float*)d_in[9];
    const float* calng = (const float*)d_in[10];
    const float* calnb = (const float*)d_in[11];
    const float* caw1  = (const float*)d_in[12];
    const float* cab1  = (const float*)d_in[13];
    const float* casc  = (const float*)d_in[14];
    const float* fw    = (const float*)d_in[15];
    const float* fb    = (const float*)d_in[16];
    float* out = (float*)d_out;

    cudaFuncSetAttribute(k2_logits, cudaFuncAttributeMaxDynamicSharedMemorySize, 208896);
    cudaFuncSetAttribute(k3_cap,    cudaFuncAttributeMaxDynamicSharedMemorySize, 208896);
    cudaFuncSetAttribute(k4_score,  cudaFuncAttributeMaxDynamicSharedMemorySize, 196736);
    cudaFuncSetAttribute(k5_pair,   cudaFuncAttributeMaxDynamicSharedMemorySize, 177632);

    k1_img<<<BV, 256>>>(img);
    k2_logits<<<392, 256, 208896>>>(img, talng, talnb, taw1, tab1, taw2, tab2);
    k3_cap<<<BT, 256, 208896>>>(cap, lens, calng, calnb, caw1, cab1, casc, fw, fb);
    k4_score<<<BV, 256, 196736>>>(img);
    k5_pair<<<dim3(BT, BV), 256, 177632>>>(img, tasc, out);
}